// round 7
// baseline (speedup 1.0000x reference)
#include <cuda_runtime.h>
#include <cstdint>

// Problem constants (fixed by the dataset)
#define NMAX 100000
#define EMAX 800000
#define DD   96

// ---------------- device scratch (no runtime allocation allowed) -------------
__device__ int   g_flag;                 // 1 = edge_index is int64
__device__ int   g_src[EMAX];
__device__ int   g_dst[EMAX];
__device__ int   g_cnt[NMAX];
__device__ int   g_scan[NMAX];           // inclusive scan of counts (per-block)
__device__ int   g_bsums[256];
__device__ int   g_rowptr[NMAX + 1];
__device__ int   g_cursor[NMAX];
__device__ int   g_dst_sorted[EMAX];
__device__ float g_h[NMAX * DD];         // post-GEMM features
__device__ float g_y1[NMAX * DD];        // layer-1 output
__device__ float g_as[NMAX];
__device__ float g_ad[NMAX];

// ---------------- dtype detection ------------------------------------------
// src begins with arange(N): int32 view of int64 data = [0,0,1,0,2,0,...]
// (odd indices are zero high-words); int32 data = [0,1,2,...].
__global__ void detect_kernel(const int* __restrict__ p) {
    if (threadIdx.x == 0) {
        bool i64 = (p[1] == 0) && (p[3] == 0) && (p[5] == 0) &&
                   (p[7] == 0) && (p[9] == 0);
        g_flag = i64 ? 1 : 0;
    }
}

__global__ void zero_cnt_kernel(int n) {
    int i = blockIdx.x * blockDim.x + threadIdx.x;
    if (i < n) g_cnt[i] = 0;
}

// convert edges to int32 and count out-degree of src
__global__ void convert_count_kernel(const void* __restrict__ eidx, int E) {
    int e = blockIdx.x * blockDim.x + threadIdx.x;
    if (e >= E) return;
    int s, d;
    if (g_flag) {
        const long long* q = (const long long*)eidx;
        s = (int)q[e];
        d = (int)q[E + e];
    } else {
        const int* q = (const int*)eidx;
        s = q[e];
        d = q[E + e];
    }
    g_src[e] = s;
    g_dst[e] = d;
    atomicAdd(&g_cnt[s], 1);
}

// ---------------- scan (counts -> rowptr) -----------------------------------
__global__ void scan_block_kernel(int n) {
    __shared__ int tmp[1024];
    int gid = blockIdx.x * 1024 + threadIdx.x;
    int v = (gid < n) ? g_cnt[gid] : 0;
    tmp[threadIdx.x] = v;
    __syncthreads();
#pragma unroll
    for (int off = 1; off < 1024; off <<= 1) {
        int t = (threadIdx.x >= off) ? tmp[threadIdx.x - off] : 0;
        __syncthreads();
        tmp[threadIdx.x] += t;
        __syncthreads();
    }
    if (gid < n) g_scan[gid] = tmp[threadIdx.x];
    if (threadIdx.x == 1023) g_bsums[blockIdx.x] = tmp[1023];
}

__global__ void scan_sums_kernel(int nb) {
    __shared__ int tmp[128];
    int v = (threadIdx.x < nb) ? g_bsums[threadIdx.x] : 0;
    tmp[threadIdx.x] = v;
    __syncthreads();
#pragma unroll
    for (int off = 1; off < 128; off <<= 1) {
        int t = (threadIdx.x >= off) ? tmp[threadIdx.x - off] : 0;
        __syncthreads();
        tmp[threadIdx.x] += t;
        __syncthreads();
    }
    if (threadIdx.x < nb) g_bsums[threadIdx.x] = tmp[threadIdx.x];
}

__global__ void finalize_rowptr_kernel(int n) {
    int i = blockIdx.x * 1024 + threadIdx.x;
    if (i >= n) return;
    int off = (blockIdx.x > 0) ? g_bsums[blockIdx.x - 1] : 0;
    int incl = g_scan[i] + off;
    int excl = incl - g_cnt[i];
    g_rowptr[i] = excl;
    g_cursor[i] = excl;
    if (i == n - 1) g_rowptr[n] = incl;
}

__global__ void fill_kernel(int E) {
    int e = blockIdx.x * blockDim.x + threadIdx.x;
    if (e >= E) return;
    int s = g_src[e];
    int p = atomicAdd(&g_cursor[s], 1);
    g_dst_sorted[p] = g_dst[e];
}

// ---------------- GEMM: H[n,96] = X[n,96] @ W[96,96] ------------------------
// BM=64 rows/block, full N=96, K chunked by 32. 256 threads,
// each thread computes 4 rows x 6 cols.
__global__ void __launch_bounds__(256) gemm96_kernel(
    const float* __restrict__ X, const float* __restrict__ W,
    float* __restrict__ H, int n)
{
    __shared__ float Ws[32 * 96];     // [k][j]
    __shared__ float Xs[64 * 33];     // [row][k], padded stride 33

    int tid = threadIdx.x;
    int ct = tid & 15;                // column group: cols [ct*6, ct*6+6)
    int rt = tid >> 4;                // row group: rows rt*4 .. rt*4+3
    int rowBase = blockIdx.x * 64;

    float acc[4][6];
#pragma unroll
    for (int i = 0; i < 4; ++i)
#pragma unroll
        for (int j = 0; j < 6; ++j) acc[i][j] = 0.f;

    for (int kc = 0; kc < 96; kc += 32) {
        // load W chunk 32x96 (idx == k*96+j, coalesced over j)
#pragma unroll
        for (int i = 0; i < 12; ++i) {
            int idx = tid + i * 256;
            Ws[idx] = W[kc * 96 + idx];
        }
        // load X tile 64x32
#pragma unroll
        for (int i = 0; i < 8; ++i) {
            int idx = tid + i * 256;
            int r = idx >> 5, k = idx & 31;
            int grow = rowBase + r;
            Xs[r * 33 + k] = (grow < n) ? X[grow * 96 + kc + k] : 0.f;
        }
        __syncthreads();

#pragma unroll
        for (int k = 0; k < 32; ++k) {
            float xr[4], wr[6];
#pragma unroll
            for (int i = 0; i < 4; ++i) xr[i] = Xs[(rt * 4 + i) * 33 + k];
#pragma unroll
            for (int j = 0; j < 6; ++j) wr[j] = Ws[k * 96 + ct * 6 + j];
#pragma unroll
            for (int i = 0; i < 4; ++i)
#pragma unroll
                for (int j = 0; j < 6; ++j) acc[i][j] += xr[i] * wr[j];
        }
        __syncthreads();
    }

#pragma unroll
    for (int i = 0; i < 4; ++i) {
        int grow = rowBase + rt * 4 + i;
        if (grow < n) {
#pragma unroll
            for (int j = 0; j < 6; ++j)
                H[grow * 96 + ct * 6 + j] = acc[i][j];
        }
    }
}

// ---------------- per-node attention scalars --------------------------------
// as[i] = h[i] . a[0:96],  ad[i] = h[i] . a[96:192]; one warp per node.
__global__ void dots_kernel(const float* __restrict__ h,
                            const float* __restrict__ a,
                            int n)
{
    int warp = (blockIdx.x * blockDim.x + threadIdx.x) >> 5;
    int lane = threadIdx.x & 31;
    if (warp >= n) return;
    const float* hr = h + (size_t)warp * 96;
    float h0 = hr[lane], h1 = hr[lane + 32], h2 = hr[lane + 64];
    float s = h0 * a[lane] + h1 * a[lane + 32] + h2 * a[lane + 64];
    float t = h0 * a[96 + lane] + h1 * a[128 + lane] + h2 * a[160 + lane];
#pragma unroll
    for (int off = 16; off > 0; off >>= 1) {
        s += __shfl_down_sync(0xffffffffu, s, off);
        t += __shfl_down_sync(0xffffffffu, t, off);
    }
    if (lane == 0) {
        g_as[warp] = s;
        g_ad[warp] = t;
    }
}

// ---------------- gather: out[i] = sum_e w_e * h[dst_e] / sum_e w_e ---------
// one warp per node; every lane computes w redundantly (broadcast loads).
__global__ void gather_kernel(const float* __restrict__ h,
                              float* __restrict__ out,
                              int n, int do_relu)
{
    int warp = (blockIdx.x * blockDim.x + threadIdx.x) >> 5;
    int lane = threadIdx.x & 31;
    if (warp >= n) return;

    int beg = g_rowptr[warp];
    int end = g_rowptr[warp + 1];
    float asi = g_as[warp];

    float a0 = 0.f, a1 = 0.f, a2 = 0.f, rs = 0.f;
    for (int p = beg; p < end; ++p) {
        int d = g_dst_sorted[p];
        float s = asi + g_ad[d];
        float lr = (s > 0.f) ? s : 0.01f * s;
        float w = __expf(-lr);
        rs += w;
        const float* hr = h + (size_t)d * 96;
        a0 += w * hr[lane];
        a1 += w * hr[lane + 32];
        a2 += w * hr[lane + 64];
    }
    float inv = (rs > 0.f) ? (1.f / rs) : 0.f;
    a0 *= inv; a1 *= inv; a2 *= inv;
    if (do_relu) {
        a0 = fmaxf(a0, 0.f);
        a1 = fmaxf(a1, 0.f);
        a2 = fmaxf(a2, 0.f);
    }
    float* o = out + (size_t)warp * 96;
    o[lane]      = a0;
    o[lane + 32] = a1;
    o[lane + 64] = a2;
}

// ---------------- launch ----------------------------------------------------
extern "C" void kernel_launch(void* const* d_in, const int* in_sizes, int n_in,
                              void* d_out, int out_size)
{
    const void*  eidx = d_in[0];
    const float* x    = (const float*)d_in[1];
    const float* W1   = (const float*)d_in[2];
    const float* a1   = (const float*)d_in[3];
    const float* W2   = (const float*)d_in[4];
    const float* a2   = (const float*)d_in[5];
    float* out = (float*)d_out;

    int E = in_sizes[0] / 2;
    int N = in_sizes[1] / DD;
    if (E > EMAX) E = EMAX;
    if (N > NMAX) N = NMAX;

    int nb = (N + 1023) / 1024;   // scan blocks (98 for N=100000, <=128)

    // ---- CSR build (shared by both layers) ----
    detect_kernel<<<1, 32>>>((const int*)eidx);
    zero_cnt_kernel<<<(N + 255) / 256, 256>>>(N);
    convert_count_kernel<<<(E + 255) / 256, 256>>>(eidx, E);
    scan_block_kernel<<<nb, 1024>>>(N);
    scan_sums_kernel<<<1, 128>>>(nb);
    finalize_rowptr_kernel<<<nb, 1024>>>(N);
    fill_kernel<<<(E + 255) / 256, 256>>>(E);

    int gemm_blocks = (N + 63) / 64;
    int warp_blocks = (N + 7) / 8;    // 8 warps (256 threads) per block

    // ---- layer 1 ----
    gemm96_kernel<<<gemm_blocks, 256>>>(x, W1, g_h, N);
    dots_kernel<<<warp_blocks, 256>>>(g_h, a1, N);
    gather_kernel<<<warp_blocks, 256>>>(g_h, g_y1, N, 0);

    // ---- layer 2 ----
    gemm96_kernel<<<gemm_blocks, 256>>>(g_y1, W2, g_h, N);
    dots_kernel<<<warp_blocks, 256>>>(g_h, a2, N);
    gather_kernel<<<warp_blocks, 256>>>(g_h, out, N, 1);
}